// round 1
// baseline (speedup 1.0000x reference)
#include <cuda_runtime.h>

// Problem shapes (static per reference setup_inputs)
#define B_RAYS 8192
#define S_LEN  512
#define K_VAL  128
#define F_DIM  32

// Fused NeRF render:
//  per valid sample v (ray b = v/128):
//    h  = relu(df[v] @ Ws0^T)        (32 -> 64)
//    dc = h @ Ws1^T                  (64 -> 16), sigma = relu(dc[0])
//    cin = [SH4(rays_d[b]) (16), dc[1:16] (15)]  (31, padded to 32)
//    c1 = relu(cin @ Wc0^T)          (31 -> 64)
//    c2 = relu(c1 @ Wc1^T)           (64 -> 64)
//    col = c2 @ Wc2^T                (64 -> 3)
//  scatter (sigma, col) to the k-th True slot of mask row b; zeros elsewhere.
__global__ __launch_bounds__(128, 4)
void nnrender_fused_kernel(const float* __restrict__ df,
                           const unsigned int* __restrict__ mask,  // 0/1 as i32 or f32 bits
                           const float* __restrict__ rays_d,
                           const float* __restrict__ Ws0,   // [64,32]
                           const float* __restrict__ Ws1,   // [16,64]
                           const float* __restrict__ Wc0,   // [64,31]
                           const float* __restrict__ Wc1,   // [64,64]
                           const float* __restrict__ Wc2,   // [3,64]
                           float* __restrict__ out)         // [B,S,4]
{
    __shared__ float sW0[64 * 32];
    __shared__ float sW1[16 * 64];
    __shared__ float sC0[64 * 32];   // Wc0 padded 31 -> 32
    __shared__ float sC1[64 * 64];
    __shared__ float sC2[3 * 64];
    __shared__ float s_sh[16];
    __shared__ unsigned short s_rank[S_LEN];   // s -> valid rank (0xffff = invalid)
    __shared__ float s_sig[K_VAL];
    __shared__ float s_col[K_VAL][3];
    __shared__ int s_scan[4];

    const int b = blockIdx.x;
    const int t = threadIdx.x;       // 0..127, one valid sample per thread
    const int lane = t & 31;
    const int warp = t >> 5;

    // ---- stage weights into shared ----
    #pragma unroll 4
    for (int i = t; i < 64 * 32; i += 128) sW0[i] = Ws0[i];
    #pragma unroll 2
    for (int i = t; i < 16 * 64; i += 128) sW1[i] = Ws1[i];
    #pragma unroll 4
    for (int i = t; i < 64 * 32; i += 128) {
        int r = i >> 5, c = i & 31;
        sC0[i] = (c < 31) ? Wc0[r * 31 + c] : 0.0f;
    }
    #pragma unroll 8
    for (int i = t; i < 64 * 64; i += 128) sC1[i] = Wc1[i];
    #pragma unroll 2
    for (int i = t; i < 3 * 64; i += 128) sC2[i] = Wc2[i];

    // ---- SH degree-4 encoding of this ray's direction (thread 0) ----
    if (t == 0) {
        float x = rays_d[b * 3 + 0], y = rays_d[b * 3 + 1], z = rays_d[b * 3 + 2];
        float x2 = x * x, y2 = y * y, z2 = z * z;
        s_sh[0]  = 0.28209479177387814f;
        s_sh[1]  = -0.48860251190291987f * y;
        s_sh[2]  =  0.48860251190291987f * z;
        s_sh[3]  = -0.48860251190291987f * x;
        s_sh[4]  =  1.0925484305920792f * x * y;
        s_sh[5]  = -1.0925484305920792f * y * z;
        s_sh[6]  =  0.94617469575755997f * z2 - 0.31539156525251999f;
        s_sh[7]  = -1.0925484305920792f * x * z;
        s_sh[8]  =  0.54627421529603959f * (x2 - y2);
        s_sh[9]  =  0.59004358992664352f * y * (-3.0f * x2 + y2);
        s_sh[10] =  2.8906114426405538f * x * y * z;
        s_sh[11] =  0.45704579946446572f * y * (1.0f - 5.0f * z2);
        s_sh[12] =  0.3731763325901154f * z * (5.0f * z2 - 3.0f);
        s_sh[13] =  0.45704579946446572f * x * (1.0f - 5.0f * z2);
        s_sh[14] =  1.445305721320277f * z * (x2 - y2);
        s_sh[15] =  0.59004358992664352f * x * (-x2 + 3.0f * y2);
    }

    // ---- mask rank scan: each thread owns 4 consecutive s positions ----
    unsigned int m[4];
    int cnt = 0;
    #pragma unroll
    for (int j = 0; j < 4; j++) {
        m[j] = mask[(size_t)b * S_LEN + t * 4 + j];
        cnt += (m[j] != 0u);
    }
    int inc = cnt;
    #pragma unroll
    for (int d = 1; d < 32; d <<= 1) {
        int n = __shfl_up_sync(0xffffffffu, inc, d);
        if (lane >= d) inc += n;
    }
    if (lane == 31) s_scan[warp] = inc;
    __syncthreads();
    int base = 0;
    #pragma unroll
    for (int w = 0; w < 4; w++) if (w < warp) base += s_scan[w];
    int ex = base + inc - cnt;       // exclusive prefix for this thread's 4 slots
    #pragma unroll
    for (int j = 0; j < 4; j++) {
        int s = t * 4 + j;
        if (m[j] != 0u) { s_rank[s] = (unsigned short)ex; ex++; }
        else            { s_rank[s] = 0xffffu; }
    }
    __syncthreads();   // weights + s_sh + s_rank all ready

    // ---- per-sample MLP ----
    const int v = b * K_VAL + t;

    float f[F_DIM];
    #pragma unroll
    for (int k = 0; k < F_DIM; k += 4) {
        float4 t4 = *reinterpret_cast<const float4*>(df + (size_t)v * F_DIM + k);
        f[k] = t4.x; f[k + 1] = t4.y; f[k + 2] = t4.z; f[k + 3] = t4.w;
    }

    // sigma_net stage 1+2 fused (8-wide h chunks to bound live registers)
    float dc[16];
    #pragma unroll
    for (int i = 0; i < 16; i++) dc[i] = 0.0f;
    #pragma unroll
    for (int j0 = 0; j0 < 64; j0 += 8) {
        float h[8];
        #pragma unroll
        for (int jj = 0; jj < 8; jj++) {
            float acc = 0.0f;
            #pragma unroll
            for (int k = 0; k < 32; k += 4) {
                float4 w = *reinterpret_cast<const float4*>(&sW0[(j0 + jj) * 32 + k]);
                acc += w.x * f[k] + w.y * f[k + 1] + w.z * f[k + 2] + w.w * f[k + 3];
            }
            h[jj] = fmaxf(acc, 0.0f);
        }
        #pragma unroll
        for (int i = 0; i < 16; i++) {
            #pragma unroll
            for (int jj = 0; jj < 8; jj += 4) {
                float4 w = *reinterpret_cast<const float4*>(&sW1[i * 64 + j0 + jj]);
                dc[i] += w.x * h[jj] + w.y * h[jj + 1] + w.z * h[jj + 2] + w.w * h[jj + 3];
            }
        }
    }
    float sigma = fmaxf(dc[0], 0.0f);

    // color input: [sh(16), dc[1:16](15), pad 0]
    float cin[32];
    #pragma unroll
    for (int i = 0; i < 16; i++) cin[i] = s_sh[i];
    #pragma unroll
    for (int i = 0; i < 15; i++) cin[16 + i] = dc[1 + i];
    cin[31] = 0.0f;

    // color_net stage 1: 31(32) -> 64
    float c1[64];
    #pragma unroll
    for (int j = 0; j < 64; j++) {
        float acc = 0.0f;
        #pragma unroll
        for (int k = 0; k < 32; k += 4) {
            float4 w = *reinterpret_cast<const float4*>(&sC0[j * 32 + k]);
            acc += w.x * cin[k] + w.y * cin[k + 1] + w.z * cin[k + 2] + w.w * cin[k + 3];
        }
        c1[j] = fmaxf(acc, 0.0f);
    }

    // color_net stage 2+3 fused (8-wide c2 chunks)
    float col0 = 0.0f, col1 = 0.0f, col2 = 0.0f;
    #pragma unroll
    for (int j0 = 0; j0 < 64; j0 += 8) {
        float c2[8];
        #pragma unroll
        for (int jj = 0; jj < 8; jj++) {
            float acc = 0.0f;
            #pragma unroll
            for (int k = 0; k < 64; k += 4) {
                float4 w = *reinterpret_cast<const float4*>(&sC1[(j0 + jj) * 64 + k]);
                acc += w.x * c1[k] + w.y * c1[k + 1] + w.z * c1[k + 2] + w.w * c1[k + 3];
            }
            c2[jj] = fmaxf(acc, 0.0f);
        }
        #pragma unroll
        for (int jj = 0; jj < 8; jj++) {
            col0 += sC2[0 * 64 + j0 + jj] * c2[jj];
            col1 += sC2[1 * 64 + j0 + jj] * c2[jj];
            col2 += sC2[2 * 64 + j0 + jj] * c2[jj];
        }
    }

    s_sig[t] = sigma;
    s_col[t][0] = col0; s_col[t][1] = col1; s_col[t][2] = col2;
    __syncthreads();

    // ---- scatter: write all 512 positions of this row (zeros where invalid) ----
    #pragma unroll
    for (int rep = 0; rep < 4; rep++) {
        int s = t + rep * 128;
        unsigned short r = s_rank[s];
        float4 o;
        if (r == 0xffffu) {
            o = make_float4(0.0f, 0.0f, 0.0f, 0.0f);
        } else {
            o = make_float4(s_sig[r], s_col[r][0], s_col[r][1], s_col[r][2]);
        }
        *reinterpret_cast<float4*>(out + ((size_t)b * S_LEN + s) * 4) = o;
    }
}

extern "C" void kernel_launch(void* const* d_in, const int* in_sizes, int n_in,
                              void* d_out, int out_size)
{
    const float*        df    = (const float*)d_in[0];        // [NV, 32]
    const unsigned int* mask  = (const unsigned int*)d_in[1]; // [B, S] 0/1 words
    const float*        rays  = (const float*)d_in[2];        // [B, 3]
    const float*        Ws0   = (const float*)d_in[3];        // [64, 32]
    const float*        Ws1   = (const float*)d_in[4];        // [16, 64]
    const float*        Wc0   = (const float*)d_in[5];        // [64, 31]
    const float*        Wc1   = (const float*)d_in[6];        // [64, 64]
    const float*        Wc2   = (const float*)d_in[7];        // [3, 64]
    float*              out   = (float*)d_out;                // [B, S, 4]

    int b_rays = in_sizes[2] / 3;    // defensive: derive B from rays_d
    if (b_rays <= 0) b_rays = B_RAYS;

    nnrender_fused_kernel<<<b_rays, 128>>>(df, mask, rays, Ws0, Ws1, Wc0, Wc1, Wc2, out);
}

// round 2
// speedup vs baseline: 2.3628x; 2.3628x over previous
#include <cuda_runtime.h>
#include <cuda_fp16.h>
#include <stdint.h>

#define S_LEN 512
#define KV    128

// SMEM strides in halves (chosen bank-conflict-free for ldmatrix / B-frag / D-store patterns)
#define ST64  72
#define ST32  40
#define STT   24

// dynamic smem layout (byte offsets, all 16B aligned)
#define OFF_X    0u        // [128][72] half  : DF -> CIN -> C2
#define OFF_Y    18432u    // [128][72] half  : H  -> C1
#define OFF_W0   36864u    // [64][40]  half  : Ws0
#define OFF_W1   41984u    // [16][72]  half  : Ws1
#define OFF_C0   44288u    // [64][40]  half  : Wc0 (col31 zero-padded)
#define OFF_C1   49408u    // [64][72]  half  : Wc1
#define OFF_C2   58624u    // [8][72]   half  : Wc2 (rows 3..7 zero)
#define OFF_T    59776u    // [128][24] half  : DC (sigma = col0)
#define OFF_COL  65920u    // [128][3]  float : colors
#define OFF_SH   67456u    // [16]      half  : SH encoding
#define OFF_RANK 67488u    // [512]     u16   : mask rank table
#define OFF_SCAN 68512u    // [4]       int
#define SMEM_BYTES 68544u

__device__ __forceinline__ uint32_t s2u(const void* p) {
    return (uint32_t)__cvta_generic_to_shared(p);
}

__device__ __forceinline__ void ldsm4(uint32_t a[4], uint32_t addr) {
    asm volatile("ldmatrix.sync.aligned.m8n8.x4.shared.b16 {%0,%1,%2,%3}, [%4];"
        : "=r"(a[0]), "=r"(a[1]), "=r"(a[2]), "=r"(a[3]) : "r"(addr));
}

__device__ __forceinline__ void mma16816(float d[4], const uint32_t a[4],
                                         uint32_t b0, uint32_t b1) {
    asm volatile("mma.sync.aligned.m16n8k16.row.col.f32.f16.f16.f32 "
        "{%0,%1,%2,%3},{%4,%5,%6,%7},{%8,%9},{%0,%1,%2,%3};"
        : "+f"(d[0]), "+f"(d[1]), "+f"(d[2]), "+f"(d[3])
        : "r"(a[0]), "r"(a[1]), "r"(a[2]), "r"(a[3]), "r"(b0), "r"(b1));
}

// One MLP layer on this warp's 32 rows: OUT[128,8*NT] (+)= A[128,16*KT] @ W^T.
// A, OUT fp16 in smem; W fp16 row-major [n][k] in smem. fp32 accumulate, optional relu.
template<int KT, int NT, int SA, int SW, int SO, bool RELU>
__device__ __forceinline__ void mlp_layer(const __half* As, const __half* Ws, __half* Os,
                                          int rowb, int lane)
{
    const int g = lane >> 2, c = lane & 3;
    const int rr = lane & 7, sub = lane >> 3;
    uint32_t a[2][KT][4];
    uint32_t abase = s2u(As);
    #pragma unroll
    for (int mt = 0; mt < 2; mt++)
        #pragma unroll
        for (int kt = 0; kt < KT; kt++) {
            uint32_t ad = abase +
                ((rowb + mt*16 + rr + (sub & 1) * 8) * SA + kt*16 + (sub >> 1) * 8) * 2;
            ldsm4(a[mt][kt], ad);
        }
    #pragma unroll
    for (int nt = 0; nt < NT; nt++) {
        float d0[4] = {0.f,0.f,0.f,0.f}, d1[4] = {0.f,0.f,0.f,0.f};
        const __half* wrow = Ws + (nt*8 + g) * SW;
        #pragma unroll
        for (int kt = 0; kt < KT; kt++) {
            uint32_t b0 = *(const uint32_t*)(wrow + kt*16 + 2*c);
            uint32_t b1 = *(const uint32_t*)(wrow + kt*16 + 2*c + 8);
            mma16816(d0, a[0][kt], b0, b1);
            mma16816(d1, a[1][kt], b0, b1);
        }
        #pragma unroll
        for (int mt = 0; mt < 2; mt++) {
            float* d = mt ? d1 : d0;
            if (RELU) {
                d[0] = fmaxf(d[0], 0.f); d[1] = fmaxf(d[1], 0.f);
                d[2] = fmaxf(d[2], 0.f); d[3] = fmaxf(d[3], 0.f);
            }
            *(__half2*)(Os + (rowb + mt*16 + g    ) * SO + nt*8 + 2*c) = __floats2half2_rn(d[0], d[1]);
            *(__half2*)(Os + (rowb + mt*16 + g + 8) * SO + nt*8 + 2*c) = __floats2half2_rn(d[2], d[3]);
        }
    }
}

__global__ __launch_bounds__(128)
void nnrender_hmma_kernel(const float* __restrict__ df,
                          const unsigned int* __restrict__ mask,
                          const float* __restrict__ rays_d,
                          const float* __restrict__ Ws0,   // [64,32]
                          const float* __restrict__ Ws1,   // [16,64]
                          const float* __restrict__ Wc0,   // [64,31]
                          const float* __restrict__ Wc1,   // [64,64]
                          const float* __restrict__ Wc2,   // [3,64]
                          float* __restrict__ out)         // [B,S,4]
{
    extern __shared__ char smem[];
    __half* sX  = (__half*)(smem + OFF_X);
    __half* sY  = (__half*)(smem + OFF_Y);
    __half* sW0 = (__half*)(smem + OFF_W0);
    __half* sW1 = (__half*)(smem + OFF_W1);
    __half* sC0 = (__half*)(smem + OFF_C0);
    __half* sC1 = (__half*)(smem + OFF_C1);
    __half* sC2 = (__half*)(smem + OFF_C2);
    __half* sT  = (__half*)(smem + OFF_T);
    float*  sCol = (float*)(smem + OFF_COL);
    __half* sSH  = (__half*)(smem + OFF_SH);
    unsigned short* sRank = (unsigned short*)(smem + OFF_RANK);
    int* sScan = (int*)(smem + OFF_SCAN);

    const int b = blockIdx.x;
    const int t = threadIdx.x;
    const int lane = t & 31;
    const int warp = t >> 5;
    const int rowb = warp * 32;

    // ---- stage weights (fp32 -> fp16) ----
    for (int i = t; i < 64 * 32; i += 128) sW0[(i >> 5) * ST32 + (i & 31)] = __float2half_rn(Ws0[i]);
    for (int i = t; i < 16 * 64; i += 128) sW1[(i >> 6) * ST64 + (i & 63)] = __float2half_rn(Ws1[i]);
    if (t < 64) {   // Wc0: K=31, pad col 31 with 0
        #pragma unroll 1
        for (int k = 0; k < 31; k++) sC0[t * ST32 + k] = __float2half_rn(Wc0[t * 31 + k]);
        sC0[t * ST32 + 31] = __half(0.f);
    }
    for (int i = t; i < 64 * 64; i += 128) sC1[(i >> 6) * ST64 + (i & 63)] = __float2half_rn(Wc1[i]);
    for (int i = t; i < 3 * 64;  i += 128) sC2[(i >> 6) * ST64 + (i & 63)] = __float2half_rn(Wc2[i]);
    for (int i = t; i < 5 * 64;  i += 128) sC2[(3 + (i >> 6)) * ST64 + (i & 63)] = __half(0.f);

    // ---- SH deg-4 encoding (thread 0) ----
    if (t == 0) {
        float x = rays_d[b*3+0], y = rays_d[b*3+1], z = rays_d[b*3+2];
        float x2 = x*x, y2 = y*y, z2 = z*z;
        float sh[16];
        sh[0]  = 0.28209479177387814f;
        sh[1]  = -0.48860251190291987f * y;
        sh[2]  =  0.48860251190291987f * z;
        sh[3]  = -0.48860251190291987f * x;
        sh[4]  =  1.0925484305920792f * x * y;
        sh[5]  = -1.0925484305920792f * y * z;
        sh[6]  =  0.94617469575755997f * z2 - 0.31539156525251999f;
        sh[7]  = -1.0925484305920792f * x * z;
        sh[8]  =  0.54627421529603959f * (x2 - y2);
        sh[9]  =  0.59004358992664352f * y * (-3.0f * x2 + y2);
        sh[10] =  2.8906114426405538f * x * y * z;
        sh[11] =  0.45704579946446572f * y * (1.0f - 5.0f * z2);
        sh[12] =  0.3731763325901154f * z * (5.0f * z2 - 3.0f);
        sh[13] =  0.45704579946446572f * x * (1.0f - 5.0f * z2);
        sh[14] =  1.445305721320277f * z * (x2 - y2);
        sh[15] =  0.59004358992664352f * x * (-x2 + 3.0f * y2);
        #pragma unroll
        for (int i = 0; i < 16; i++) sSH[i] = __float2half_rn(sh[i]);
    }

    // ---- DF row -> sX (fp16) ----
    {
        const float4* src = (const float4*)(df + (size_t)(b * KV + t) * 32);
        __half* xr = sX + t * ST64;
        #pragma unroll
        for (int j = 0; j < 8; j++) {
            float4 v = src[j];
            *(__half2*)(xr + j*4)     = __floats2half2_rn(v.x, v.y);
            *(__half2*)(xr + j*4 + 2) = __floats2half2_rn(v.z, v.w);
        }
    }

    // ---- mask rank scan (4 positions per thread) ----
    unsigned int m[4];
    int cnt = 0;
    #pragma unroll
    for (int j = 0; j < 4; j++) {
        m[j] = mask[(size_t)b * S_LEN + t*4 + j];
        cnt += (m[j] != 0u);
    }
    int inc = cnt;
    #pragma unroll
    for (int d = 1; d < 32; d <<= 1) {
        int n = __shfl_up_sync(0xffffffffu, inc, d);
        if (lane >= d) inc += n;
    }
    if (lane == 31) sScan[warp] = inc;
    __syncthreads();
    int base = 0;
    #pragma unroll
    for (int w = 0; w < 4; w++) if (w < warp) base += sScan[w];
    int ex = base + inc - cnt;
    #pragma unroll
    for (int j = 0; j < 4; j++) {
        int s = t*4 + j;
        if (m[j] != 0u) { sRank[s] = (unsigned short)ex; ex++; }
        else            { sRank[s] = 0xffffu; }
    }
    __syncthreads();   // weights + DF + SH + rank all visible

    // ---- G1: H = relu(DF @ Ws0^T)  [128,32]x[32,64] -> sY ----
    mlp_layer<2, 8, ST64, ST32, ST64, true>(sX, sW0, sY, rowb, lane);
    __syncwarp();

    // ---- G2: DC = H @ Ws1^T  [128,64]x[64,16] -> sT (raw) ----
    mlp_layer<4, 2, ST64, ST64, STT, false>(sY, sW1, sT, rowb, lane);
    __syncwarp();

    // ---- repack: CIN = [SH(16), DC[1:16](15), 0] -> sX ----
    {
        const uint32_t* shp = (const uint32_t*)sSH;    // 8 uniform pairs
        const uint32_t* tp  = (const uint32_t*)(sT + t * STT);
        uint32_t p[16];
        #pragma unroll
        for (int j = 0; j < 8; j++) p[j] = shp[j];
        uint32_t tr[8];
        #pragma unroll
        for (int j = 0; j < 8; j++) tr[j] = tp[j];
        #pragma unroll
        for (int j = 0; j < 7; j++) p[8 + j] = (tr[j] >> 16) | (tr[j + 1] << 16);
        p[15] = tr[7] >> 16;                           // (dc15, 0)
        uint32_t* xr = (uint32_t*)(sX + t * ST64);
        #pragma unroll
        for (int j = 0; j < 16; j++) xr[j] = p[j];
    }
    __syncwarp();

    // ---- G3: C1 = relu(CIN @ Wc0^T) -> sY ----
    mlp_layer<2, 8, ST64, ST32, ST64, true>(sX, sC0, sY, rowb, lane);
    __syncwarp();

    // ---- G4: C2 = relu(C1 @ Wc1^T) -> sX ----
    mlp_layer<4, 8, ST64, ST64, ST64, true>(sY, sC1, sX, rowb, lane);
    __syncwarp();

    // ---- G5: COL = C2 @ Wc2^T  [128,64]x[64,3] -> sCol (fp32) ----
    {
        const int g = lane >> 2, c = lane & 3;
        const int rr = lane & 7, sub = lane >> 3;
        uint32_t abase = s2u(sX);
        #pragma unroll
        for (int mt = 0; mt < 2; mt++) {
            uint32_t a[4][4];
            #pragma unroll
            for (int kt = 0; kt < 4; kt++) {
                uint32_t ad = abase +
                    ((rowb + mt*16 + rr + (sub & 1) * 8) * ST64 + kt*16 + (sub >> 1) * 8) * 2;
                ldsm4(a[kt], ad);
            }
            float d[4] = {0.f,0.f,0.f,0.f};
            const __half* wrow = sC2 + g * ST64;
            #pragma unroll
            for (int kt = 0; kt < 4; kt++) {
                uint32_t b0 = *(const uint32_t*)(wrow + kt*16 + 2*c);
                uint32_t b1 = *(const uint32_t*)(wrow + kt*16 + 2*c + 8);
                mma16816(d, a[kt], b0, b1);
            }
            int r0 = rowb + mt*16 + g;
            if (c == 0) {
                sCol[r0*3 + 0] = d[0];  sCol[r0*3 + 1] = d[1];
                sCol[(r0+8)*3 + 0] = d[2];  sCol[(r0+8)*3 + 1] = d[3];
            } else if (c == 1) {
                sCol[r0*3 + 2] = d[0];
                sCol[(r0+8)*3 + 2] = d[2];
            }
        }
    }
    __syncthreads();

    // ---- scatter: all 512 positions of this row ----
    #pragma unroll
    for (int rep = 0; rep < 4; rep++) {
        int s = t + rep * 128;
        unsigned short r = sRank[s];
        float4 o;
        if (r == 0xffffu) {
            o = make_float4(0.f, 0.f, 0.f, 0.f);
        } else {
            float sig = fmaxf(__half2float(sT[(int)r * STT]), 0.f);
            o = make_float4(sig, sCol[r*3 + 0], sCol[r*3 + 1], sCol[r*3 + 2]);
        }
        *reinterpret_cast<float4*>(out + ((size_t)b * S_LEN + s) * 4) = o;
    }
}

extern "C" void kernel_launch(void* const* d_in, const int* in_sizes, int n_in,
                              void* d_out, int out_size)
{
    const float*        df    = (const float*)d_in[0];
    const unsigned int* mask  = (const unsigned int*)d_in[1];
    const float*        rays  = (const float*)d_in[2];
    const float*        Ws0   = (const float*)d_in[3];
    const float*        Ws1   = (const float*)d_in[4];
    const float*        Wc0   = (const float*)d_in[5];
    const float*        Wc1   = (const float*)d_in[6];
    const float*        Wc2   = (const float*)d_in[7];
    float*              out   = (float*)d_out;

    int b_rays = in_sizes[2] / 3;
    if (b_rays <= 0) b_rays = 8192;

    cudaFuncSetAttribute(nnrender_hmma_kernel,
                         cudaFuncAttributeMaxDynamicSharedMemorySize, SMEM_BYTES);
    nnrender_hmma_kernel<<<b_rays, 128, SMEM_BYTES>>>(df, mask, rays,
                                                      Ws0, Ws1, Wc0, Wc1, Wc2, out);
}

// round 3
// speedup vs baseline: 6.1467x; 2.6014x over previous
#include <cuda_runtime.h>
#include <cuda_fp16.h>
#include <stdint.h>

#define S_LEN 512
#define KV    128
#define RPB   8          // rays per block

// smem strides in halves (bank-conflict-free, validated in R2)
#define ST64  72
#define ST32  40
#define STX   40

__device__ __forceinline__ uint32_t s2u(const void* p) {
    return (uint32_t)__cvta_generic_to_shared(p);
}
__device__ __forceinline__ void ldsm4(uint32_t a[4], uint32_t addr) {
    asm volatile("ldmatrix.sync.aligned.m8n8.x4.shared.b16 {%0,%1,%2,%3}, [%4];"
        : "=r"(a[0]), "=r"(a[1]), "=r"(a[2]), "=r"(a[3]) : "r"(addr));
}
__device__ __forceinline__ void mma16816(float* d, const uint32_t* a,
                                         uint32_t b0, uint32_t b1) {
    asm volatile("mma.sync.aligned.m16n8k16.row.col.f32.f16.f16.f32 "
        "{%0,%1,%2,%3},{%4,%5,%6,%7},{%8,%9},{%0,%1,%2,%3};"
        : "+f"(d[0]), "+f"(d[1]), "+f"(d[2]), "+f"(d[3])
        : "r"(a[0]), "r"(a[1]), "r"(a[2]), "r"(a[3]), "r"(b0), "r"(b1));
}
__device__ __forceinline__ uint32_t h2nr(float a, float b) {
    __half2 h = __floats2half2_rn(a, b);
    return *(uint32_t*)&h;
}
__device__ __forceinline__ uint32_t h2relu(float a, float b) {
    __half2 h = __floats2half2_rn(fmaxf(a, 0.f), fmaxf(b, 0.f));
    return *(uint32_t*)&h;
}

// OUT[2*NT][4] = A[2*KT][4] @ W^T-from-smem (fp32 accum, zero-init)
template<int KT, int NT, int SW>
__device__ __forceinline__ void layer(const uint32_t* A, const __half* W,
                                      int g, int c, float* acc)
{
    #pragma unroll
    for (int i = 0; i < 2 * NT * 4; i++) acc[i] = 0.f;
    #pragma unroll
    for (int nt = 0; nt < NT; nt++) {
        const __half* wrow = W + (nt * 8 + g) * SW;
        #pragma unroll
        for (int kt = 0; kt < KT; kt++) {
            uint32_t b0 = *(const uint32_t*)(wrow + kt * 16 + 2 * c);
            uint32_t b1 = *(const uint32_t*)(wrow + kt * 16 + 2 * c + 8);
            mma16816(acc + (0 * NT + nt) * 4, A + (0 * KT + kt) * 4, b0, b1);
            mma16816(acc + (1 * NT + nt) * 4, A + (1 * KT + kt) * 4, b0, b1);
        }
    }
}

// pack accumulators (N = 8*NT) into next layer's A fragments (K = 8*NT), with relu
template<int NT>
__device__ __forceinline__ void pack_relu(const float* acc, uint32_t* Aout)
{
    #pragma unroll
    for (int mt = 0; mt < 2; mt++)
        #pragma unroll
        for (int kt = 0; kt < NT / 2; kt++) {
            const float* a0 = acc + (mt * NT + 2 * kt) * 4;
            const float* a1 = acc + (mt * NT + 2 * kt + 1) * 4;
            uint32_t* o = Aout + (mt * (NT / 2) + kt) * 4;
            o[0] = h2relu(a0[0], a0[1]);
            o[1] = h2relu(a0[2], a0[3]);
            o[2] = h2relu(a1[0], a1[1]);
            o[3] = h2relu(a1[2], a1[3]);
        }
}

// SH deg-4 values (sh[2c], sh[2c+1], sh[2c+8], sh[2c+9]) for this lane's c
__device__ __forceinline__ float4 sh_vals(float x, float y, float z, int c)
{
    float x2 = x * x, y2 = y * y, z2 = z * z;
    float4 r;
    switch (c) {
    case 0:
        r.x = 0.28209479177387814f;
        r.y = -0.48860251190291987f * y;
        r.z = 0.54627421529603959f * (x2 - y2);
        r.w = 0.59004358992664352f * y * (-3.0f * x2 + y2);
        break;
    case 1:
        r.x = 0.48860251190291987f * z;
        r.y = -0.48860251190291987f * x;
        r.z = 2.8906114426405538f * x * y * z;
        r.w = 0.45704579946446572f * y * (1.0f - 5.0f * z2);
        break;
    case 2:
        r.x = 1.0925484305920792f * x * y;
        r.y = -1.0925484305920792f * y * z;
        r.z = 0.3731763325901154f * z * (5.0f * z2 - 3.0f);
        r.w = 0.45704579946446572f * x * (1.0f - 5.0f * z2);
        break;
    default:
        r.x = 0.94617469575755997f * z2 - 0.31539156525251999f;
        r.y = -1.0925484305920792f * x * z;
        r.z = 1.445305721320277f * z * (x2 - y2);
        r.w = 0.59004358992664352f * x * (-x2 + 3.0f * y2);
        break;
    }
    return r;
}

__global__ __launch_bounds__(128, 4)
void nnrender_reg_kernel(const float* __restrict__ df,
                         const unsigned int* __restrict__ mask,
                         const float* __restrict__ rays_d,
                         const float* __restrict__ Ws0,   // [64,32]
                         const float* __restrict__ Ws1,   // [16,64]
                         const float* __restrict__ Wc0,   // [64,31]
                         const float* __restrict__ Wc1,   // [64,64]
                         const float* __restrict__ Wc2,   // [3,64]
                         float* __restrict__ out)         // [B,S,4]
{
    __shared__ __align__(16) __half sX[128 * STX];     // DF staging (warp-private rows)
    __shared__ __align__(16) __half sW0[64 * ST32];
    __shared__ __align__(16) __half sW1[16 * ST64];
    __shared__ __align__(16) __half sC0[64 * ST32];    // col 31 zero-padded
    __shared__ __align__(16) __half sC1[64 * ST64];
    __shared__ __align__(16) __half sC2[8 * ST64];     // rows 3..7 zero
    __shared__ __align__(16) float  sOut[2][128][4];   // sigma + rgb, double-buffered
    __shared__ int sScan[2][4];

    const int t = threadIdx.x;
    const int lane = t & 31;
    const int warp = t >> 5;
    const int rowb = warp * 32;
    const int g = lane >> 2, c = lane & 3;
    const int rr = lane & 7, sub = lane >> 3;

    // ---- stage weights once (fp32 -> fp16) ----
    for (int i = t; i < 64 * 32; i += 128) sW0[(i >> 5) * ST32 + (i & 31)] = __float2half_rn(Ws0[i]);
    for (int i = t; i < 16 * 64; i += 128) sW1[(i >> 6) * ST64 + (i & 63)] = __float2half_rn(Ws1[i]);
    if (t < 64) {
        #pragma unroll 1
        for (int k = 0; k < 31; k++) sC0[t * ST32 + k] = __float2half_rn(Wc0[t * 31 + k]);
        sC0[t * ST32 + 31] = __half(0.f);
    }
    for (int i = t; i < 64 * 64; i += 128) sC1[(i >> 6) * ST64 + (i & 63)] = __float2half_rn(Wc1[i]);
    for (int i = t; i < 3 * 64;  i += 128) sC2[(i >> 6) * ST64 + (i & 63)] = __float2half_rn(Wc2[i]);
    for (int i = t; i < 5 * 64;  i += 128) sC2[(3 + (i >> 6)) * ST64 + (i & 63)] = __half(0.f);
    __syncthreads();

    const int ray0 = blockIdx.x * RPB;

    #pragma unroll 1
    for (int it = 0; it < RPB; it++) {
        const int ray = ray0 + it;
        const int buf = it & 1;

        // ---- issue mask + ray-dir + DF loads early ----
        unsigned int m[4];
        #pragma unroll
        for (int j = 0; j < 4; j++) m[j] = mask[(size_t)ray * S_LEN + t * 4 + j];
        float rx = rays_d[ray * 3 + 0], ry = rays_d[ray * 3 + 1], rz = rays_d[ray * 3 + 2];

        // DF row t -> sX (fp16), warp-private rows
        {
            const float4* src = (const float4*)(df + (size_t)(ray * KV + t) * 32);
            uint32_t p[16];
            #pragma unroll
            for (int j = 0; j < 8; j++) {
                float4 v = src[j];
                p[2 * j]     = h2nr(v.x, v.y);
                p[2 * j + 1] = h2nr(v.z, v.w);
            }
            uint4* xr = (uint4*)(sX + t * STX);
            #pragma unroll
            for (int j = 0; j < 4; j++)
                xr[j] = make_uint4(p[4 * j], p[4 * j + 1], p[4 * j + 2], p[4 * j + 3]);
        }
        __syncwarp();

        // ---- warp scan of mask counts (cross-warp combine after the one sync) ----
        int cnt = (m[0] != 0u) + (m[1] != 0u) + (m[2] != 0u) + (m[3] != 0u);
        int inc = cnt;
        #pragma unroll
        for (int d = 1; d < 32; d <<= 1) {
            int n = __shfl_up_sync(0xffffffffu, inc, d);
            if (lane >= d) inc += n;
        }
        if (lane == 31) sScan[buf][warp] = inc;

        // ---- L1: H = relu(DF @ Ws0^T), A via ldmatrix ----
        uint32_t A1[2 * 2 * 4];
        {
            uint32_t abase = s2u(sX);
            #pragma unroll
            for (int mt = 0; mt < 2; mt++)
                #pragma unroll
                for (int kt = 0; kt < 2; kt++) {
                    uint32_t ad = abase +
                        ((rowb + mt * 16 + rr + (sub & 1) * 8) * STX + kt * 16 + (sub >> 1) * 8) * 2;
                    ldsm4(A1 + (mt * 2 + kt) * 4, ad);
                }
        }
        float acc[2 * 8 * 4];
        layer<2, 8, ST32>(A1, sW0, g, c, acc);
        uint32_t A2[2 * 4 * 4];
        pack_relu<8>(acc, A2);

        // ---- L2: DC = H @ Ws1^T (raw, fp32 in regs) ----
        float dcacc[2 * 2 * 4];
        layer<4, 2, ST64>(A2, sW1, g, c, dcacc);

        // sigma = relu(dc[0]) -> sOut fp32 (held by c==0 lanes)
        if (c == 0) {
            #pragma unroll
            for (int mt = 0; mt < 2; mt++) {
                sOut[buf][rowb + mt * 16 + g][0]     = fmaxf(dcacc[(mt * 2) * 4 + 0], 0.f);
                sOut[buf][rowb + mt * 16 + g + 8][0] = fmaxf(dcacc[(mt * 2) * 4 + 2], 0.f);
            }
        }

        // ---- CIN = [SH(16), dc[1:16], 0] as register A fragments ----
        uint32_t A3[2 * 2 * 4];
        {
            float4 shv = sh_vals(rx, ry, rz, c);
            uint32_t shp01 = h2nr(shv.x, shv.y);
            uint32_t shp89 = h2nr(shv.z, shv.w);
            const int src = (lane & ~3) | ((c + 1) & 3);
            #pragma unroll
            for (int mt = 0; mt < 2; mt++) {
                const float* d0 = dcacc + (mt * 2 + 0) * 4;   // dc cols 0..7
                const float* d1 = dcacc + (mt * 2 + 1) * 4;   // dc cols 8..15
                float n00 = __shfl_sync(0xffffffffu, d0[0], src);
                float n02 = __shfl_sync(0xffffffffu, d0[2], src);
                float n10 = __shfl_sync(0xffffffffu, d1[0], src);
                float n12 = __shfl_sync(0xffffffffu, d1[2], src);
                bool last = (c == 3);
                float s0 = last ? n10 : n00;   // dc[2c+2]  (row g)
                float s1 = last ? n12 : n02;   // dc[2c+2]  (row g+8)
                float s2 = last ? 0.f : n10;   // dc[2c+10] (row g)   [col31 -> 0]
                float s3 = last ? 0.f : n12;   // dc[2c+10] (row g+8)
                uint32_t* p = A3 + (mt * 2 + 0) * 4;   // kt=0: SH (row-independent)
                p[0] = shp01; p[1] = shp01; p[2] = shp89; p[3] = shp89;
                uint32_t* o = A3 + (mt * 2 + 1) * 4;   // kt=1: dc[1:16]
                o[0] = h2nr(d0[1], s0);
                o[1] = h2nr(d0[3], s1);
                o[2] = h2nr(d1[1], s2);
                o[3] = h2nr(d1[3], s3);
            }
        }

        // ---- L3: C1 = relu(CIN @ Wc0^T) ----
        layer<2, 8, ST32>(A3, sC0, g, c, acc);
        uint32_t A4[2 * 4 * 4];
        pack_relu<8>(acc, A4);

        // ---- L4: C2 = relu(C1 @ Wc1^T) ----
        layer<4, 8, ST64>(A4, sC1, g, c, acc);
        uint32_t A5[2 * 4 * 4];
        pack_relu<8>(acc, A5);

        // ---- L5: COL = C2 @ Wc2^T (N=3 in an n8 tile) ----
        float acc5[2 * 1 * 4];
        layer<4, 1, ST64>(A5, sC2, g, c, acc5);
        if (c == 0) {
            #pragma unroll
            for (int mt = 0; mt < 2; mt++) {
                int r = rowb + mt * 16 + g;
                sOut[buf][r][1]     = acc5[mt * 4 + 0];
                sOut[buf][r][2]     = acc5[mt * 4 + 1];
                sOut[buf][r + 8][1] = acc5[mt * 4 + 2];
                sOut[buf][r + 8][2] = acc5[mt * 4 + 3];
            }
        } else if (c == 1) {
            #pragma unroll
            for (int mt = 0; mt < 2; mt++) {
                int r = rowb + mt * 16 + g;
                sOut[buf][r][3]     = acc5[mt * 4 + 0];
                sOut[buf][r + 8][3] = acc5[mt * 4 + 2];
            }
        }

        __syncthreads();   // sOut + sScan visible; also protects prev-buf WAR

        // ---- scatter: thread owns output slots 4t..4t+3 ----
        int ex = inc - cnt;
        if (warp > 0) ex += sScan[buf][0];
        if (warp > 1) ex += sScan[buf][1];
        if (warp > 2) ex += sScan[buf][2];
        float4* dst = (float4*)(out + ((size_t)ray * S_LEN + 4 * t) * 4);
        #pragma unroll
        for (int j = 0; j < 4; j++) {
            float4 o = make_float4(0.f, 0.f, 0.f, 0.f);
            if (m[j] != 0u) {
                o = *(const float4*)sOut[buf][ex];
                ex++;
            }
            dst[j] = o;
        }
    }
}

extern "C" void kernel_launch(void* const* d_in, const int* in_sizes, int n_in,
                              void* d_out, int out_size)
{
    const float*        df    = (const float*)d_in[0];
    const unsigned int* mask  = (const unsigned int*)d_in[1];
    const float*        rays  = (const float*)d_in[2];
    const float*        Ws0   = (const float*)d_in[3];
    const float*        Ws1   = (const float*)d_in[4];
    const float*        Wc0   = (const float*)d_in[5];
    const float*        Wc1   = (const float*)d_in[6];
    const float*        Wc2   = (const float*)d_in[7];
    float*              out   = (float*)d_out;

    int b_rays = in_sizes[2] / 3;
    if (b_rays <= 0) b_rays = 8192;
    int blocks = b_rays / RPB;

    nnrender_reg_kernel<<<blocks, 128>>>(df, mask, rays, Ws0, Ws1, Wc0, Wc1, Wc2, out);
}

// round 4
// speedup vs baseline: 9.0738x; 1.4762x over previous
#include <cuda_runtime.h>
#include <cuda_fp16.h>
#include <stdint.h>

#define S_LEN 512
#define KV    128
#define RPB   4          // rays per block

__device__ __forceinline__ void mma16816(float* d, const uint32_t* a,
                                         uint32_t b0, uint32_t b1) {
    asm volatile("mma.sync.aligned.m16n8k16.row.col.f32.f16.f16.f32 "
        "{%0,%1,%2,%3},{%4,%5,%6,%7},{%8,%9},{%0,%1,%2,%3};"
        : "+f"(d[0]), "+f"(d[1]), "+f"(d[2]), "+f"(d[3])
        : "r"(a[0]), "r"(a[1]), "r"(a[2]), "r"(a[3]), "r"(b0), "r"(b1));
}
__device__ __forceinline__ uint32_t h2nr(float a, float b) {
    __half2 h = __floats2half2_rn(a, b);
    return *(uint32_t*)&h;
}
__device__ __forceinline__ uint32_t h2relu(float a, float b) {
    __half2 h = __floats2half2_rn(a, b);
    h = __hmax2(h, __half2_raw{0, 0});
    return *(uint32_t*)&h;
}

// Repack W[n][k] (row-major, nrows x kin, zero-padded) into lane-packed
// B-fragment blocks: block (nt*KT+kt), lane l=(g*4+c) holds halves
// {W[nt*8+g][kt*16+2c], [2c+1], [2c+8], [2c+9]} at dst + blk*128 + l*4.
template<int NT, int KT>
__device__ __forceinline__ void stage_w(const float* __restrict__ W, int nrows, int kin,
                                        __half* dst, int t)
{
    for (int idx = t; idx < NT * KT * 32; idx += 128) {
        int blk = idx >> 5, ln = idx & 31;
        int kt = blk % KT, nt = blk / KT;
        int n = nt * 8 + (ln >> 2);
        int k0 = kt * 16 + 2 * (ln & 3);
        float v[4];
        #pragma unroll
        for (int i = 0; i < 4; i++) {
            int k = k0 + (i & 1) + (i & 2) * 4;
            v[i] = (n < nrows && k < kin) ? W[n * kin + k] : 0.f;
        }
        uint2 p;
        p.x = h2nr(v[0], v[1]);
        p.y = h2nr(v[2], v[3]);
        *(uint2*)(dst + blk * 128 + ln * 4) = p;
    }
}

// acc[2*NT][4] = A[2*KT][4] @ Wp (lane-packed), fp32 accum, zero-init
template<int KT, int NT>
__device__ __forceinline__ void layerP(const uint32_t* A, const __half* Wp,
                                       int lane, float* acc)
{
    #pragma unroll
    for (int i = 0; i < 2 * NT * 4; i++) acc[i] = 0.f;
    #pragma unroll
    for (int nt = 0; nt < NT; nt++) {
        #pragma unroll
        for (int kt = 0; kt < KT; kt++) {
            uint2 b = *(const uint2*)(Wp + (nt * KT + kt) * 128 + lane * 4);
            mma16816(acc + (0 * NT + nt) * 4, A + (0 * KT + kt) * 4, b.x, b.y);
            mma16816(acc + (1 * NT + nt) * 4, A + (1 * KT + kt) * 4, b.x, b.y);
        }
    }
}

// pack NT(=4) n8-tiles of accumulators into A fragments (KTO k16-tile stride),
// starting at k-tile ktbase, with relu
template<int NT, int KTO>
__device__ __forceinline__ void pack_relu2(const float* acc, uint32_t* Aout, int ktbase)
{
    #pragma unroll
    for (int mt = 0; mt < 2; mt++)
        #pragma unroll
        for (int kt = 0; kt < NT / 2; kt++) {
            const float* a0 = acc + (mt * NT + 2 * kt) * 4;
            const float* a1 = acc + (mt * NT + 2 * kt + 1) * 4;
            uint32_t* o = Aout + (mt * KTO + ktbase + kt) * 4;
            o[0] = h2relu(a0[0], a0[1]);
            o[1] = h2relu(a0[2], a0[3]);
            o[2] = h2relu(a1[0], a1[1]);
            o[3] = h2relu(a1[2], a1[3]);
        }
}

// SH deg-4 values (sh[2c], sh[2c+1], sh[2c+8], sh[2c+9]) for this lane's c
__device__ __forceinline__ float4 sh_vals(float x, float y, float z, int c)
{
    float x2 = x * x, y2 = y * y, z2 = z * z;
    float4 r;
    switch (c) {
    case 0:
        r.x = 0.28209479177387814f;
        r.y = -0.48860251190291987f * y;
        r.z = 0.54627421529603959f * (x2 - y2);
        r.w = 0.59004358992664352f * y * (-3.0f * x2 + y2);
        break;
    case 1:
        r.x = 0.48860251190291987f * z;
        r.y = -0.48860251190291987f * x;
        r.z = 2.8906114426405538f * x * y * z;
        r.w = 0.45704579946446572f * y * (1.0f - 5.0f * z2);
        break;
    case 2:
        r.x = 1.0925484305920792f * x * y;
        r.y = -1.0925484305920792f * y * z;
        r.z = 0.3731763325901154f * z * (5.0f * z2 - 3.0f);
        r.w = 0.45704579946446572f * x * (1.0f - 5.0f * z2);
        break;
    default:
        r.x = 0.94617469575755997f * z2 - 0.31539156525251999f;
        r.y = -1.0925484305920792f * x * z;
        r.z = 1.445305721320277f * z * (x2 - y2);
        r.w = 0.59004358992664352f * x * (-x2 + 3.0f * y2);
        break;
    }
    return r;
}

__global__ __launch_bounds__(128, 5)
void nnrender_packed_kernel(const float* __restrict__ df,
                            const unsigned int* __restrict__ mask,
                            const float* __restrict__ rays_d,
                            const float* __restrict__ Ws0,   // [64,32]
                            const float* __restrict__ Ws1,   // [16,64]
                            const float* __restrict__ Wc0,   // [64,31]
                            const float* __restrict__ Wc1,   // [64,64]
                            const float* __restrict__ Wc2,   // [3,64]
                            float* __restrict__ out)         // [B,S,4]
{
    // lane-packed weights (halves): blk*128 + lane*4
    __shared__ __align__(16) __half sW0[8 * 2 * 128];   // NT=8 KT=2
    __shared__ __align__(16) __half sW1[2 * 4 * 128];   // NT=2 KT=4
    __shared__ __align__(16) __half sC0[8 * 2 * 128];   // NT=8 KT=2 (k=31 pad)
    __shared__ __align__(16) __half sC1[8 * 4 * 128];   // NT=8 KT=4
    __shared__ __align__(16) __half sC2[1 * 4 * 128];   // NT=1 KT=4 (n=3 pad)
    __shared__ __align__(16) float  sOut[2][128][4];
    __shared__ int sScan[2][4];

    const int t = threadIdx.x;
    const int lane = t & 31;
    const int warp = t >> 5;
    const int rowb = warp * 32;
    const int g = lane >> 2, c = lane & 3;

    // ---- stage + repack weights once per block ----
    stage_w<8, 2>(Ws0, 64, 32, sW0, t);
    stage_w<2, 4>(Ws1, 16, 64, sW1, t);
    stage_w<8, 2>(Wc0, 64, 31, sC0, t);
    stage_w<8, 4>(Wc1, 64, 64, sC1, t);
    stage_w<1, 4>(Wc2,  3, 64, sC2, t);
    __syncthreads();

    const int ray0 = blockIdx.x * RPB;

    #pragma unroll 1
    for (int it = 0; it < RPB; it++) {
        const int ray = ray0 + it;
        const int buf = it & 1;

        // ---- early loads: mask, ray dir, DF fragments (high MLP) ----
        uint4 mv = *(const uint4*)(mask + (size_t)ray * S_LEN + t * 4);
        float rx = rays_d[ray * 3 + 0], ry = rays_d[ray * 3 + 1], rz = rays_d[ray * 3 + 2];

        uint32_t A1[2 * 2 * 4];
        {
            const float* dfr = df + (size_t)(ray * KV) * 32 + 2 * c;
            #pragma unroll
            for (int mt = 0; mt < 2; mt++)
                #pragma unroll
                for (int half = 0; half < 2; half++) {
                    const float* rp = dfr + (rowb + mt * 16 + g + half * 8) * 32;
                    #pragma unroll
                    for (int kt = 0; kt < 2; kt++) {
                        float2 v0 = *(const float2*)(rp + kt * 16);
                        float2 v1 = *(const float2*)(rp + kt * 16 + 8);
                        A1[(mt * 2 + kt) * 4 + half]     = h2nr(v0.x, v0.y);
                        A1[(mt * 2 + kt) * 4 + 2 + half] = h2nr(v1.x, v1.y);
                    }
                }
        }

        // ---- mask scan ----
        int cnt = (mv.x != 0u) + (mv.y != 0u) + (mv.z != 0u) + (mv.w != 0u);
        int inc = cnt;
        #pragma unroll
        for (int d = 1; d < 32; d <<= 1) {
            int n = __shfl_up_sync(0xffffffffu, inc, d);
            if (lane >= d) inc += n;
        }
        if (lane == 31) sScan[buf][warp] = inc;

        // ---- L1: H = relu(DF @ Ws0^T), two 32-wide passes ----
        float acc[2 * 4 * 4];
        uint32_t A2[2 * 4 * 4];
        layerP<2, 4>(A1, sW0, lane, acc);
        pack_relu2<4, 4>(acc, A2, 0);
        layerP<2, 4>(A1, sW0 + 4 * 2 * 128, lane, acc);
        pack_relu2<4, 4>(acc, A2, 2);

        // ---- L2: DC = H @ Ws1^T (raw fp32) ----
        float dcacc[2 * 2 * 4];
        layerP<4, 2>(A2, sW1, lane, dcacc);

        // sigma = relu(dc[0]) (c==0 lanes)
        if (c == 0) {
            #pragma unroll
            for (int mt = 0; mt < 2; mt++) {
                sOut[buf][rowb + mt * 16 + g][0]     = fmaxf(dcacc[(mt * 2) * 4 + 0], 0.f);
                sOut[buf][rowb + mt * 16 + g + 8][0] = fmaxf(dcacc[(mt * 2) * 4 + 2], 0.f);
            }
        }

        // ---- CIN = [SH(16), dc[1:16], 0] as A fragments (KT=2) ----
        uint32_t A3[2 * 2 * 4];
        {
            float4 shv = sh_vals(rx, ry, rz, c);
            uint32_t shp01 = h2nr(shv.x, shv.y);
            uint32_t shp89 = h2nr(shv.z, shv.w);
            const int src = (lane & ~3) | ((c + 1) & 3);
            #pragma unroll
            for (int mt = 0; mt < 2; mt++) {
                const float* d0 = dcacc + (mt * 2 + 0) * 4;   // dc cols 0..7
                const float* d1 = dcacc + (mt * 2 + 1) * 4;   // dc cols 8..15
                float n00 = __shfl_sync(0xffffffffu, d0[0], src);
                float n02 = __shfl_sync(0xffffffffu, d0[2], src);
                float n10 = __shfl_sync(0xffffffffu, d1[0], src);
                float n12 = __shfl_sync(0xffffffffu, d1[2], src);
                bool last = (c == 3);
                float s0 = last ? n10 : n00;
                float s1 = last ? n12 : n02;
                float s2 = last ? 0.f : n10;
                float s3 = last ? 0.f : n12;
                uint32_t* p = A3 + (mt * 2 + 0) * 4;   // kt=0: SH (row-independent)
                p[0] = shp01; p[1] = shp01; p[2] = shp89; p[3] = shp89;
                uint32_t* o = A3 + (mt * 2 + 1) * 4;   // kt=1: dc[1:16]
                o[0] = h2nr(d0[1], s0);
                o[1] = h2nr(d0[3], s1);
                o[2] = h2nr(d1[1], s2);
                o[3] = h2nr(d1[3], s3);
            }
        }

        // ---- L3: C1 = relu(CIN @ Wc0^T), two passes ----
        uint32_t A4[2 * 4 * 4];
        layerP<2, 4>(A3, sC0, lane, acc);
        pack_relu2<4, 4>(acc, A4, 0);
        layerP<2, 4>(A3, sC0 + 4 * 2 * 128, lane, acc);
        pack_relu2<4, 4>(acc, A4, 2);

        // ---- L4: C2 = relu(C1 @ Wc1^T), two passes ----
        uint32_t A5[2 * 4 * 4];
        layerP<4, 4>(A4, sC1, lane, acc);
        pack_relu2<4, 4>(acc, A5, 0);
        layerP<4, 4>(A4, sC1 + 4 * 4 * 128, lane, acc);
        pack_relu2<4, 4>(acc, A5, 2);

        // ---- L5: COL = C2 @ Wc2^T ----
        float acc5[2 * 1 * 4];
        layerP<4, 1>(A5, sC2, lane, acc5);
        if (c == 0) {
            #pragma unroll
            for (int mt = 0; mt < 2; mt++) {
                int r = rowb + mt * 16 + g;
                sOut[buf][r][1]     = acc5[mt * 4 + 0];
                sOut[buf][r][2]     = acc5[mt * 4 + 1];
                sOut[buf][r + 8][1] = acc5[mt * 4 + 2];
                sOut[buf][r + 8][2] = acc5[mt * 4 + 3];
            }
        } else if (c == 1) {
            #pragma unroll
            for (int mt = 0; mt < 2; mt++) {
                int r = rowb + mt * 16 + g;
                sOut[buf][r][3]     = acc5[mt * 4 + 0];
                sOut[buf][r + 8][3] = acc5[mt * 4 + 2];
            }
        }

        __syncthreads();

        // ---- scatter: thread owns output slots 4t..4t+3 ----
        int ex = inc - cnt;
        if (warp > 0) ex += sScan[buf][0];
        if (warp > 1) ex += sScan[buf][1];
        if (warp > 2) ex += sScan[buf][2];
        float4* dst = (float4*)(out + ((size_t)ray * S_LEN + 4 * t) * 4);
        unsigned int mm[4] = {mv.x, mv.y, mv.z, mv.w};
        #pragma unroll
        for (int j = 0; j < 4; j++) {
            float4 o = make_float4(0.f, 0.f, 0.f, 0.f);
            if (mm[j] != 0u) {
                o = *(const float4*)sOut[buf][ex];
                ex++;
            }
            dst[j] = o;
        }
    }
}

extern "C" void kernel_launch(void* const* d_in, const int* in_sizes, int n_in,
                              void* d_out, int out_size)
{
    const float*        df    = (const float*)d_in[0];
    const unsigned int* mask  = (const unsigned int*)d_in[1];
    const float*        rays  = (const float*)d_in[2];
    const float*        Ws0   = (const float*)d_in[3];
    const float*        Ws1   = (const float*)d_in[4];
    const float*        Wc0   = (const float*)d_in[5];
    const float*        Wc1   = (const float*)d_in[6];
    const float*        Wc2   = (const float*)d_in[7];
    float*              out   = (float*)d_out;

    int b_rays = in_sizes[2] / 3;
    if (b_rays <= 0) b_rays = 8192;
    int blocks = (b_rays + RPB - 1) / RPB;

    nnrender_packed_kernel<<<blocks, 128>>>(df, mask, rays, Ws0, Ws1, Wc0, Wc1, Wc2, out);
}

// round 5
// speedup vs baseline: 10.6351x; 1.1721x over previous
#include <cuda_runtime.h>
#include <cuda_fp16.h>
#include <stdint.h>

#define S_LEN 512
#define KV    128
#define NBLK  740        // 148 SMs x 5 resident blocks (persistent)

// fused weight arena offsets (halves); each "block" = 256 halves (paired kt tiles)
#define OW0 0        // NT=8 KTP=1 -> 8 blocks  (2048)
#define OW1 2048     // NT=2 KTP=2 -> 4 blocks  (1024)
#define OC0 3072     // NT=8 KTP=1 -> 8 blocks  (2048)
#define OC1 5120     // NT=8 KTP=2 -> 16 blocks (4096)
#define OC2 9216     // NT=1 KTP=2 -> 2 blocks  (512)
#define WTOT 9728

__device__ __forceinline__ void mma16816(float* d, const uint32_t* a,
                                         uint32_t b0, uint32_t b1) {
    asm volatile("mma.sync.aligned.m16n8k16.row.col.f32.f16.f16.f32 "
        "{%0,%1,%2,%3},{%4,%5,%6,%7},{%8,%9},{%0,%1,%2,%3};"
        : "+f"(d[0]), "+f"(d[1]), "+f"(d[2]), "+f"(d[3])
        : "r"(a[0]), "r"(a[1]), "r"(a[2]), "r"(a[3]), "r"(b0), "r"(b1));
}
__device__ __forceinline__ uint32_t h2nr(float a, float b) {
    __half2 h = __floats2half2_rn(a, b);
    return *(uint32_t*)&h;
}
__device__ __forceinline__ uint32_t h2relu(float a, float b) {
    __half2 h = __floats2half2_rn(a, b);
    h = __hmax2(h, __half2_raw{0, 0});
    return *(uint32_t*)&h;
}

// Repack W[n][k] into paired-kt lane-packed blocks.
// Block (nt*KTP+ktp) = 256 halves; lane l=(g*4+c) holds uint4:
//   {b0,b1 of kt=2ktp , b0,b1 of kt=2ktp+1} where b0=(W[n][2c],W[n][2c+1]),
//   b1=(W[n][2c+8],W[n][2c+9]) in k-slot space. PERM: k-slot (kt,i)->col 8c+4kt+i.
template<int NT, int KT, bool PERM>
__device__ __forceinline__ void stage_w(const float* __restrict__ W, int nrows, int kin,
                                        __half* dst, int t)
{
    constexpr int KTP = KT / 2;
    for (int idx = t; idx < NT * KTP * 32; idx += 128) {
        int blk = idx >> 5, ln = idx & 31;
        int ktp = blk % KTP, nt = blk / KTP;
        int n = nt * 8 + (ln >> 2);
        int cc = ln & 3;
        uint32_t p[4];
        #pragma unroll
        for (int h = 0; h < 2; h++) {
            int kt = 2 * ktp + h;
            float v[4];
            #pragma unroll
            for (int i = 0; i < 4; i++) {
                int k = PERM ? (8 * cc + 4 * kt + i)
                             : (kt * 16 + 2 * cc + (i & 1) + (i >> 1) * 8);
                v[i] = (n < nrows && k < kin) ? W[n * kin + k] : 0.f;
            }
            p[2 * h]     = h2nr(v[0], v[1]);
            p[2 * h + 1] = h2nr(v[2], v[3]);
        }
        *(uint4*)(dst + blk * 256 + ln * 8) = make_uint4(p[0], p[1], p[2], p[3]);
    }
}

// acc[2*NT][4] = A[2*KT][4] @ W (paired lane-packed, WpLane = base + lane*8)
template<int KT, int NT>
__device__ __forceinline__ void layerP(const uint32_t* A, const __half* WpLane, float* acc)
{
    constexpr int KTP = KT / 2;
    #pragma unroll
    for (int i = 0; i < 2 * NT * 4; i++) acc[i] = 0.f;
    #pragma unroll
    for (int nt = 0; nt < NT; nt++) {
        #pragma unroll
        for (int ktp = 0; ktp < KTP; ktp++) {
            uint4 b = *(const uint4*)(WpLane + (nt * KTP + ktp) * 256);
            mma16816(acc + (0 * NT + nt) * 4, A + (0 * KT + 2 * ktp) * 4, b.x, b.y);
            mma16816(acc + (1 * NT + nt) * 4, A + (1 * KT + 2 * ktp) * 4, b.x, b.y);
            mma16816(acc + (0 * NT + nt) * 4, A + (0 * KT + 2 * ktp + 1) * 4, b.z, b.w);
            mma16816(acc + (1 * NT + nt) * 4, A + (1 * KT + 2 * ktp + 1) * 4, b.z, b.w);
        }
    }
}

// pack NT(=4) n8-tiles of accumulators into A fragments, with relu
template<int NT, int KTO>
__device__ __forceinline__ void pack_relu2(const float* acc, uint32_t* Aout, int ktbase)
{
    #pragma unroll
    for (int mt = 0; mt < 2; mt++)
        #pragma unroll
        for (int kt = 0; kt < NT / 2; kt++) {
            const float* a0 = acc + (mt * NT + 2 * kt) * 4;
            const float* a1 = acc + (mt * NT + 2 * kt + 1) * 4;
            uint32_t* o = Aout + (mt * KTO + ktbase + kt) * 4;
            o[0] = h2relu(a0[0], a0[1]);
            o[1] = h2relu(a0[2], a0[3]);
            o[2] = h2relu(a1[0], a1[1]);
            o[3] = h2relu(a1[2], a1[3]);
        }
}

// SH deg-4 values (sh[2c], sh[2c+1], sh[2c+8], sh[2c+9]) for this lane's c
__device__ __forceinline__ float4 sh_vals(float x, float y, float z, int c)
{
    float x2 = x * x, y2 = y * y, z2 = z * z;
    float4 r;
    switch (c) {
    case 0:
        r.x = 0.28209479177387814f;
        r.y = -0.48860251190291987f * y;
        r.z = 0.54627421529603959f * (x2 - y2);
        r.w = 0.59004358992664352f * y * (-3.0f * x2 + y2);
        break;
    case 1:
        r.x = 0.48860251190291987f * z;
        r.y = -0.48860251190291987f * x;
        r.z = 2.8906114426405538f * x * y * z;
        r.w = 0.45704579946446572f * y * (1.0f - 5.0f * z2);
        break;
    case 2:
        r.x = 1.0925484305920792f * x * y;
        r.y = -1.0925484305920792f * y * z;
        r.z = 0.3731763325901154f * z * (5.0f * z2 - 3.0f);
        r.w = 0.45704579946446572f * x * (1.0f - 5.0f * z2);
        break;
    default:
        r.x = 0.94617469575755997f * z2 - 0.31539156525251999f;
        r.y = -1.0925484305920792f * x * z;
        r.z = 1.445305721320277f * z * (x2 - y2);
        r.w = 0.59004358992664352f * x * (-x2 + 3.0f * y2);
        break;
    }
    return r;
}

__global__ __launch_bounds__(128, 5)
void nnrender_persist_kernel(const float* __restrict__ df,
                             const unsigned int* __restrict__ mask,
                             const float* __restrict__ rays_d,
                             const float* __restrict__ Ws0,   // [64,32]
                             const float* __restrict__ Ws1,   // [16,64]
                             const float* __restrict__ Wc0,   // [64,31]
                             const float* __restrict__ Wc1,   // [64,64]
                             const float* __restrict__ Wc2,   // [3,64]
                             float* __restrict__ out,         // [B,S,4]
                             int n_rays)
{
    __shared__ __align__(16) __half sW[WTOT];
    __shared__ __align__(16) float  sOut[2][128][4];
    __shared__ int sScan[2][4];

    const int t = threadIdx.x;
    const int lane = t & 31;
    const int warp = t >> 5;
    const int rowb = warp * 32;
    const int g = lane >> 2, c = lane & 3;

    // ---- stage + repack weights once per (persistent) block ----
    stage_w<8, 2, true >(Ws0, 64, 32, sW + OW0, t);   // permuted K (matches DF loads)
    stage_w<2, 4, false>(Ws1, 16, 64, sW + OW1, t);
    stage_w<8, 2, false>(Wc0, 64, 31, sW + OC0, t);
    stage_w<8, 4, false>(Wc1, 64, 64, sW + OC1, t);
    stage_w<1, 4, false>(Wc2,  3, 64, sW + OC2, t);
    __syncthreads();

    const __half* wL = sW + lane * 8;   // per-lane base; constexpr offsets below

    int it = 0;
    #pragma unroll 1
    for (int ray = blockIdx.x; ray < n_rays; ray += gridDim.x, it++) {
        const int buf = it & 1;

        // ---- early loads: mask, ray dir, DF fragments (permuted-K, LDG.128) ----
        uint4 mv = *(const uint4*)(mask + (size_t)ray * S_LEN + t * 4);
        float rx = rays_d[ray * 3 + 0], ry = rays_d[ray * 3 + 1], rz = rays_d[ray * 3 + 2];

        uint32_t A1[2 * 2 * 4];
        {
            const float* dfr = df + (size_t)(ray * KV) * 32 + 8 * c;
            #pragma unroll
            for (int mt = 0; mt < 2; mt++)
                #pragma unroll
                for (int half = 0; half < 2; half++) {
                    const float* rp = dfr + (rowb + mt * 16 + g + half * 8) * 32;
                    float4 v0 = *(const float4*)(rp);       // k-slots (2c,2c+1,2c+8,2c+9) kt0
                    float4 v1 = *(const float4*)(rp + 4);   // same, kt1
                    A1[(mt * 2 + 0) * 4 + half]     = h2nr(v0.x, v0.y);
                    A1[(mt * 2 + 0) * 4 + 2 + half] = h2nr(v0.z, v0.w);
                    A1[(mt * 2 + 1) * 4 + half]     = h2nr(v1.x, v1.y);
                    A1[(mt * 2 + 1) * 4 + 2 + half] = h2nr(v1.z, v1.w);
                }
        }

        // ---- mask scan ----
        int cnt = (mv.x != 0u) + (mv.y != 0u) + (mv.z != 0u) + (mv.w != 0u);
        int inc = cnt;
        #pragma unroll
        for (int d = 1; d < 32; d <<= 1) {
            int n = __shfl_up_sync(0xffffffffu, inc, d);
            if (lane >= d) inc += n;
        }
        if (lane == 31) sScan[buf][warp] = inc;

        // ---- L1: H = relu(DF @ Ws0^T), two 32-wide passes ----
        float acc[2 * 4 * 4];
        uint32_t A2[2 * 4 * 4];
        layerP<2, 4>(A1, wL + OW0, acc);
        pack_relu2<4, 4>(acc, A2, 0);
        layerP<2, 4>(A1, wL + OW0 + 4 * 256, acc);
        pack_relu2<4, 4>(acc, A2, 2);

        // ---- L2: DC = H @ Ws1^T (raw fp32) ----
        float dcacc[2 * 2 * 4];
        layerP<4, 2>(A2, wL + OW1, dcacc);

        // sigma = relu(dc[0]) (c==0 lanes)
        if (c == 0) {
            #pragma unroll
            for (int mt = 0; mt < 2; mt++) {
                sOut[buf][rowb + mt * 16 + g][0]     = fmaxf(dcacc[(mt * 2) * 4 + 0], 0.f);
                sOut[buf][rowb + mt * 16 + g + 8][0] = fmaxf(dcacc[(mt * 2) * 4 + 2], 0.f);
            }
        }

        // ---- CIN = [SH(16), dc[1:16], 0] as A fragments (KT=2) ----
        uint32_t A3[2 * 2 * 4];
        {
            float4 shv = sh_vals(rx, ry, rz, c);
            uint32_t shp01 = h2nr(shv.x, shv.y);
            uint32_t shp89 = h2nr(shv.z, shv.w);
            const int src = (lane & ~3) | ((c + 1) & 3);
            #pragma unroll
            for (int mt = 0; mt < 2; mt++) {
                const float* d0 = dcacc + (mt * 2 + 0) * 4;   // dc cols 0..7
                const float* d1 = dcacc + (mt * 2 + 1) * 4;   // dc cols 8..15
                float n00 = __shfl_sync(0xffffffffu, d0[0], src);
                float n02 = __shfl_sync(0xffffffffu, d0[2], src);
                float n10 = __shfl_sync(0xffffffffu, d1[0], src);
                float n12 = __shfl_sync(0xffffffffu, d1[2], src);
                bool last = (c == 3);
                float s0 = last ? n10 : n00;
                float s1 = last ? n12 : n02;
                float s2 = last ? 0.f : n10;
                float s3 = last ? 0.f : n12;
                uint32_t* p = A3 + (mt * 2 + 0) * 4;   // kt=0: SH (row-independent)
                p[0] = shp01; p[1] = shp01; p[2] = shp89; p[3] = shp89;
                uint32_t* o = A3 + (mt * 2 + 1) * 4;   // kt=1: dc[1:16]
                o[0] = h2nr(d0[1], s0);
                o[1] = h2nr(d0[3], s1);
                o[2] = h2nr(d1[1], s2);
                o[3] = h2nr(d1[3], s3);
            }
        }

        // ---- L3: C1 = relu(CIN @ Wc0^T), two passes ----
        uint32_t A4[2 * 4 * 4];
        layerP<2, 4>(A3, wL + OC0, acc);
        pack_relu2<4, 4>(acc, A4, 0);
        layerP<2, 4>(A3, wL + OC0 + 4 * 256, acc);
        pack_relu2<4, 4>(acc, A4, 2);

        // ---- L4: C2 = relu(C1 @ Wc1^T), two passes ----
        uint32_t A5[2 * 4 * 4];
        layerP<4, 4>(A4, wL + OC1, acc);
        pack_relu2<4, 4>(acc, A5, 0);
        layerP<4, 4>(A4, wL + OC1 + 8 * 256, acc);
        pack_relu2<4, 4>(acc, A5, 2);

        // ---- L5: COL = C2 @ Wc2^T ----
        float acc5[2 * 1 * 4];
        layerP<4, 1>(A5, wL + OC2, acc5);
        if (c == 0) {
            #pragma unroll
            for (int mt = 0; mt < 2; mt++) {
                int r = rowb + mt * 16 + g;
                sOut[buf][r][1]     = acc5[mt * 4 + 0];
                sOut[buf][r][2]     = acc5[mt * 4 + 1];
                sOut[buf][r + 8][1] = acc5[mt * 4 + 2];
                sOut[buf][r + 8][2] = acc5[mt * 4 + 3];
            }
        } else if (c == 1) {
            #pragma unroll
            for (int mt = 0; mt < 2; mt++) {
                int r = rowb + mt * 16 + g;
                sOut[buf][r][3]     = acc5[mt * 4 + 0];
                sOut[buf][r + 8][3] = acc5[mt * 4 + 2];
            }
        }

        __syncthreads();

        // ---- scatter: thread owns output slots 4t..4t+3 ----
        int ex = inc - cnt;
        if (warp > 0) ex += sScan[buf][0];
        if (warp > 1) ex += sScan[buf][1];
        if (warp > 2) ex += sScan[buf][2];
        float4* dst = (float4*)(out + ((size_t)ray * S_LEN + 4 * t) * 4);
        unsigned int mm[4] = {mv.x, mv.y, mv.z, mv.w};
        #pragma unroll
        for (int j = 0; j < 4; j++) {
            float4 o = make_float4(0.f, 0.f, 0.f, 0.f);
            if (mm[j] != 0u) {
                o = *(const float4*)sOut[buf][ex];
                ex++;
            }
            dst[j] = o;
        }
    }
}

extern "C" void kernel_launch(void* const* d_in, const int* in_sizes, int n_in,
                              void* d_out, int out_size)
{
    const float*        df    = (const float*)d_in[0];
    const unsigned int* mask  = (const unsigned int*)d_in[1];
    const float*        rays  = (const float*)d_in[2];
    const float*        Ws0   = (const float*)d_in[3];
    const float*        Ws1   = (const float*)d_in[4];
    const float*        Wc0   = (const float*)d_in[5];
    const float*        Wc1   = (const float*)d_in[6];
    const float*        Wc2   = (const float*)d_in[7];
    float*              out   = (float*)d_out;

    int b_rays = in_sizes[2] / 3;
    if (b_rays <= 0) b_rays = 8192;
    int blocks = NBLK < b_rays ? NBLK : b_rays;

    nnrender_persist_kernel<<<blocks, 128>>>(df, mask, rays,
                                             Ws0, Ws1, Wc0, Wc1, Wc2, out, b_rays);
}